// round 13
// baseline (speedup 1.0000x reference)
#include <cuda_runtime.h>
#include <cuda_fp16.h>
#include <cstdint>
#include <cstddef>

// Problem constants
#define D_MODEL 1024
#define F_DIM   4096
#define NEXP    8
#define NTOK    8192
#define MAXM    8192

// GEMM tiling: CTA 128x128x64, 4 warps (2x2), warp tile 64x64, 3-stage cp.async
#define BM 128
#define BN 128
#define BK 64
#define NST 3
#define A_BYTES (BM * BK * 2)        // 16384
#define B_BYTES (BN * BK * 2)        // 16384
#define STG_B   (A_BYTES + B_BYTES)  // 32768
#define SMEM_REQ (NST * STG_B)       // 98304

#define NW4 (NEXP * F_DIM * D_MODEL / 4)   // 8,388,608 float4 per weight tensor
#define NO4 (NTOK * D_MODEL / 4)           // 2,097,152 float4 in output
#define TOT4 (2 * NW4 + NO4)

// ---------------- scratch (device globals) ----------------
__device__ int   g_counts[NEXP];
__device__ int   g_tokens[NEXP * MAXM];
__device__ float g_gatew[NEXP * MAXM];
__device__ __align__(16) __half g_xh [(size_t)NTOK * D_MODEL];
__device__ __align__(16) __half g_w1h[(size_t)NEXP * F_DIM * D_MODEL];
__device__ __align__(16) __half g_w2h[(size_t)NEXP * D_MODEL * F_DIM];
__device__ __align__(16) __half g_H  [(size_t)NEXP * MAXM * F_DIM];

// ---------------- PTX helpers ----------------
__device__ __forceinline__ uint32_t smem_u32(const void* p) {
    return (uint32_t)__cvta_generic_to_shared(p);
}
__device__ __forceinline__ void cp_async16(uint32_t dst, const void* src) {
    asm volatile("cp.async.cg.shared.global [%0], [%1], 16;\n" :: "r"(dst), "l"(src));
}
__device__ __forceinline__ void cp_commit() { asm volatile("cp.async.commit_group;\n"); }
__device__ __forceinline__ void cp_wait1()  { asm volatile("cp.async.wait_group 1;\n"); }

__device__ __forceinline__ void ldm4(uint32_t& r0, uint32_t& r1, uint32_t& r2, uint32_t& r3, uint32_t a) {
    asm volatile("ldmatrix.sync.aligned.m8n8.x4.shared.b16 {%0,%1,%2,%3}, [%4];"
                 : "=r"(r0), "=r"(r1), "=r"(r2), "=r"(r3) : "r"(a));
}
__device__ __forceinline__ void mma_16816(float* c, const uint32_t* a, const uint32_t* b) {
    asm volatile("mma.sync.aligned.m16n8k16.row.col.f32.f16.f16.f32 "
                 "{%0,%1,%2,%3}, {%4,%5,%6,%7}, {%8,%9}, {%0,%1,%2,%3};"
                 : "+f"(c[0]), "+f"(c[1]), "+f"(c[2]), "+f"(c[3])
                 : "r"(a[0]), "r"(a[1]), "r"(a[2]), "r"(a[3]), "r"(b[0]), "r"(b[1]));
}

// ------- prep: counts reset + w1/w2 fp32->fp16 + zero d_out (all DRAM-bound) ---
__global__ void prep_kernel(const float* __restrict__ w1, const float* __restrict__ w2,
                            float* __restrict__ out) {
    if (blockIdx.x == 0 && threadIdx.x < NEXP) g_counts[threadIdx.x] = 0;
    int i = blockIdx.x * 256 + threadIdx.x;
    const int stride = gridDim.x * 256;
#pragma unroll 1
    for (; i < TOT4; i += stride) {
        if (i < 2 * NW4) {
            const bool second = (i >= NW4);
            const int  j      = second ? i - NW4 : i;
            const float4 v = ((const float4*)(second ? w2 : w1))[j];
            __half2* d2 = (__half2*)(second ? g_w2h : g_w1h) + 2 * (size_t)j;
            d2[0] = __floats2half2_rn(v.x, v.y);
            d2[1] = __floats2half2_rn(v.z, v.w);
        } else {
            ((float4*)out)[i - 2 * NW4] = make_float4(0.f, 0.f, 0.f, 0.f);
        }
    }
}

// ---------------- routing (gw staged in smem, float4 x, fused x->fp16) --------
__global__ void __launch_bounds__(256) gate_kernel(const float* __restrict__ x,
                                                   const float* __restrict__ gw) {
    __shared__ float sgw[NEXP][D_MODEL / 4][4];
#pragma unroll
    for (int i = threadIdx.x; i < NEXP * D_MODEL / 4; i += 256) {
        const float4 v = ((const float4*)gw)[i];
        const int e = i >> 8, d4 = i & 255;
        sgw[e][d4][0] = v.x; sgw[e][d4][1] = v.y;
        sgw[e][d4][2] = v.z; sgw[e][d4][3] = v.w;
    }
    __syncthreads();

    const int lane  = threadIdx.x & 31;
    const int token = blockIdx.x * 8 + (threadIdx.x >> 5);

    const float4* xr = (const float4*)(x + (size_t)token * D_MODEL);
    uint2*        xh = (uint2*)(g_xh + (size_t)token * D_MODEL);
    float acc[NEXP];
#pragma unroll
    for (int e = 0; e < NEXP; e++) acc[e] = 0.f;

#pragma unroll
    for (int it = 0; it < D_MODEL / 4 / 32; it++) {       // 8 iters
        const int d4 = lane + it * 32;
        const float4 v = xr[d4];
        __half2 h0 = __floats2half2_rn(v.x, v.y);
        __half2 h1 = __floats2half2_rn(v.z, v.w);
        xh[d4] = make_uint2(*(uint32_t*)&h0, *(uint32_t*)&h1);
#pragma unroll
        for (int e = 0; e < NEXP; e++)
            acc[e] += v.x * sgw[e][d4][0] + v.y * sgw[e][d4][1]
                    + v.z * sgw[e][d4][2] + v.w * sgw[e][d4][3];
    }
#pragma unroll
    for (int e = 0; e < NEXP; e++) {
#pragma unroll
        for (int off = 16; off > 0; off >>= 1)
            acc[e] += __shfl_xor_sync(0xFFFFFFFFu, acc[e], off);
    }
    if (lane == 0) {
        float v0 = -1e30f, v1 = -1e30f;
        int   i0 = 0,      i1 = 0;
#pragma unroll
        for (int e = 0; e < NEXP; e++) {
            const float v = acc[e];
            if (v > v0)      { v1 = v0; i1 = i0; v0 = v; i0 = e; }
            else if (v > v1) { v1 = v;  i1 = e; }
        }
        const float p0 = 1.f / (1.f + __expf(v1 - v0));
        const float p1 = 1.f - p0;
        int s0 = atomicAdd(&g_counts[i0], 1);
        g_tokens[i0 * MAXM + s0] = token;
        g_gatew [i0 * MAXM + s0] = p0;
        int s1 = atomicAdd(&g_counts[i1], 1);
        g_tokens[i1 * MAXM + s1] = token;
        g_gatew [i1 * MAXM + s1] = p1;
    }
}

// ---------------- grouped FFN GEMM (r8 configuration) ----------------
// SECOND=false: H[r,:] = relu(X[tok(r),:] @ W1[e]^T)          K=1024, N=4096
// SECOND=true : out[tok(r),:] += gate(r)*(H[r,:] @ W2[e]^T)   K=4096, N=1024
template <bool SECOND>
__global__ void __launch_bounds__(128, 2) ffn_kernel(float* __restrict__ out) {
    extern __shared__ __align__(128) char sm[];
    __shared__ const __half* srcA[BM];

    const int e   = blockIdx.z;
    const int cnt = g_counts[e];
    const int m0  = blockIdx.x * BM;
    if (m0 >= cnt) return;
    const int n0  = blockIdx.y * BN;
    constexpr int KDIM = SECOND ? F_DIM : D_MODEL;
    constexpr int KT   = KDIM / BK;

    const int tid    = threadIdx.x;
    const int lane   = tid & 31;
    const int wid    = tid >> 5;
    const int warp_m = wid & 1;        // 2 warps in M (64 rows each)
    const int warp_n = (wid >> 1) & 1; // 2 warps in N (64 cols each)

    {
        int r = m0 + tid; if (r >= cnt) r = cnt - 1;
        srcA[tid] = SECOND ? g_H + ((size_t)e * MAXM + r) * F_DIM
                           : g_xh + (size_t)g_tokens[e * MAXM + r] * D_MODEL;
    }
    __syncthreads();

    const __half*  wb  = (SECOND ? g_w2h : g_w1h) + (size_t)e * F_DIM * D_MODEL;
    const uint32_t smb = smem_u32(sm);

    auto load_stage = [&](int st, int kt) {
        const uint32_t aw = smb + st * STG_B;
        const uint32_t bw = aw + A_BYTES;
        const int k0 = kt * BK;
#pragma unroll
        for (int i = 0; i < 8; i++) {                   // A: 1024 16B chunks / 128 thr
            const int idx = tid + i * 128;
            const int row = idx >> 3, c = idx & 7;
            cp_async16(aw + row * 128 + ((c ^ (row & 7)) << 4), srcA[row] + k0 + c * 8);
        }
#pragma unroll
        for (int i = 0; i < 8; i++) {                   // B: 1024 16B chunks
            const int idx = tid + i * 128;
            const int row = idx >> 3, c = idx & 7;
            cp_async16(bw + row * 128 + ((c ^ (row & 7)) << 4),
                       wb + (size_t)(n0 + row) * KDIM + k0 + c * 8);
        }
    };

    auto load_frags = [&](int s, uint32_t (*af)[4], uint32_t (*bf)[2],
                          uint32_t ab, uint32_t bb) {
        const int kk8 = s * 2;
#pragma unroll
        for (int mt = 0; mt < 4; mt++) {
            const int row = warp_m * 64 + mt * 16 + (lane & 15);
            const int k8  = kk8 + (lane >> 4);
            ldm4(af[mt][0], af[mt][1], af[mt][2], af[mt][3],
                 ab + row * 128 + ((k8 ^ (row & 7)) << 4));
        }
#pragma unroll
        for (int i = 0; i < 4; i++) {        // each ldm4 -> two n8k16 B frags
            const int row = warp_n * 64 + i * 16 + ((lane >> 4) << 3) + (lane & 7);
            const int k8  = kk8 + ((lane >> 3) & 1);
            ldm4(bf[2 * i][0], bf[2 * i][1], bf[2 * i + 1][0], bf[2 * i + 1][1],
                 bb + row * 128 + ((k8 ^ (row & 7)) << 4));
        }
    };

    float acc[4][8][4] = {};

    load_stage(0, 0); cp_commit();
    load_stage(1, 1); cp_commit();

#pragma unroll 1
    for (int kt = 0; kt < KT; kt++) {
        cp_wait1();
        __syncthreads();

        const int kn = kt + 2;
        if (kn < KT) load_stage(kn % NST, kn);
        cp_commit();

        const uint32_t ab = smb + (kt % NST) * STG_B;
        const uint32_t bb = ab + A_BYTES;

        uint32_t af[2][4][4], bf[2][8][2];
        load_frags(0, af[0], bf[0], ab, bb);
#pragma unroll
        for (int s = 0; s < 4; s++) {            // 4 k16 steps, double-buffered frags
            if (s < 3) load_frags(s + 1, af[(s + 1) & 1], bf[(s + 1) & 1], ab, bb);
            const int cur = s & 1;
#pragma unroll
            for (int mt = 0; mt < 4; mt++)
#pragma unroll
                for (int nt = 0; nt < 8; nt++)
                    mma_16816(acc[mt][nt], af[cur][mt], bf[cur][nt]);
        }
    }

    // ---- epilogue ----
    const int rbase = m0 + warp_m * 64 + (lane >> 2);
    const int cb    = n0 + warp_n * 64 + (lane & 3) * 2;
    if (!SECOND) {
#pragma unroll
        for (int mt = 0; mt < 4; mt++)
#pragma unroll
            for (int half = 0; half < 2; half++) {
                const int r = rbase + mt * 16 + half * 8;
                if (r < cnt) {
                    __half* hrow = g_H + ((size_t)e * MAXM + r) * F_DIM;
#pragma unroll
                    for (int nt = 0; nt < 8; nt++) {
                        const float v0 = fmaxf(acc[mt][nt][half * 2 + 0], 0.f);
                        const float v1 = fmaxf(acc[mt][nt][half * 2 + 1], 0.f);
                        *(__half2*)&hrow[cb + nt * 8] = __floats2half2_rn(v0, v1);
                    }
                }
            }
    } else {
#pragma unroll
        for (int mt = 0; mt < 4; mt++)
#pragma unroll
            for (int half = 0; half < 2; half++) {
                const int r = rbase + mt * 16 + half * 8;
                if (r < cnt) {
                    const int   tok = g_tokens[e * MAXM + r];
                    const float gwv = g_gatew[e * MAXM + r];
                    float* orow = out + (size_t)tok * D_MODEL;
#pragma unroll
                    for (int nt = 0; nt < 8; nt++) {
                        atomicAdd(&orow[cb + nt * 8 + 0], acc[mt][nt][half * 2 + 0] * gwv);
                        atomicAdd(&orow[cb + nt * 8 + 1], acc[mt][nt][half * 2 + 1] * gwv);
                    }
                }
            }
    }
}

// ---------------- launch ----------------
extern "C" void kernel_launch(void* const* d_in, const int* in_sizes, int n_in,
                              void* d_out, int out_size) {
    const float* x   = (const float*)d_in[0];
    const float* gw  = (const float*)d_in[1];
    const float* w1  = (const float*)d_in[2];
    const float* w2  = (const float*)d_in[3];
    float*       out = (float*)d_out;

    cudaFuncSetAttribute(ffn_kernel<false>, cudaFuncAttributeMaxDynamicSharedMemorySize, SMEM_REQ);
    cudaFuncSetAttribute(ffn_kernel<true>,  cudaFuncAttributeMaxDynamicSharedMemorySize, SMEM_REQ);

    prep_kernel<<<18432, 256>>>(w1, w2, out);   // counts reset + w1/w2 convert + zero out
    gate_kernel<<<NTOK / 8, 256>>>(x, gw);      // routes + converts x

    ffn_kernel<false><<<dim3(MAXM / BM, F_DIM / BN, NEXP), 128, SMEM_REQ>>>(nullptr);
    ffn_kernel<true ><<<dim3(MAXM / BM, D_MODEL / BN, NEXP), 128, SMEM_REQ>>>(out);
}

// round 14
// speedup vs baseline: 1.5077x; 1.5077x over previous
#include <cuda_runtime.h>
#include <cuda_fp16.h>
#include <cstdint>
#include <cstddef>

// Problem constants
#define D_MODEL 1024
#define F_DIM   4096
#define NEXP    8
#define NTOK    8192
#define MAXM    8192

// GEMM tiling: CTA 128x128x64, 4 warps (2x2), warp tile 64x64, 3-stage cp.async
#define BM 128
#define BN 128
#define BK 64
#define NST 3
#define A_BYTES (BM * BK * 2)        // 16384
#define B_BYTES (BN * BK * 2)        // 16384
#define STG_B   (A_BYTES + B_BYTES)  // 32768
#define SMEM_REQ (NST * STG_B)       // 98304

#define NW4 (NEXP * F_DIM * D_MODEL / 4)   // 8,388,608 float4 per weight tensor
#define NO4 (NTOK * D_MODEL / 4)           // 2,097,152 float4 in output
#define TOT4 (2 * NW4 + NO4)

// ---------------- scratch (device globals) ----------------
__device__ int   g_counts[NEXP];
__device__ int   g_tokens[NEXP * MAXM];
__device__ float g_gatew[NEXP * MAXM];
__device__ __align__(16) __half g_xh [(size_t)NTOK * D_MODEL];
__device__ __align__(16) __half g_w1h[(size_t)NEXP * F_DIM * D_MODEL];
__device__ __align__(16) __half g_w2h[(size_t)NEXP * D_MODEL * F_DIM];
__device__ __align__(16) __half g_H  [(size_t)NEXP * MAXM * F_DIM];

// ---------------- PTX helpers ----------------
__device__ __forceinline__ uint32_t smem_u32(const void* p) {
    return (uint32_t)__cvta_generic_to_shared(p);
}
__device__ __forceinline__ void cp_async16(uint32_t dst, const void* src) {
    asm volatile("cp.async.cg.shared.global [%0], [%1], 16;\n" :: "r"(dst), "l"(src));
}
__device__ __forceinline__ void cp_commit() { asm volatile("cp.async.commit_group;\n"); }
__device__ __forceinline__ void cp_wait1()  { asm volatile("cp.async.wait_group 1;\n"); }

__device__ __forceinline__ void ldm4(uint32_t& r0, uint32_t& r1, uint32_t& r2, uint32_t& r3, uint32_t a) {
    asm volatile("ldmatrix.sync.aligned.m8n8.x4.shared.b16 {%0,%1,%2,%3}, [%4];"
                 : "=r"(r0), "=r"(r1), "=r"(r2), "=r"(r3) : "r"(a));
}
__device__ __forceinline__ void mma_16816(float* c, const uint32_t* a, const uint32_t* b) {
    asm volatile("mma.sync.aligned.m16n8k16.row.col.f32.f16.f16.f32 "
                 "{%0,%1,%2,%3}, {%4,%5,%6,%7}, {%8,%9}, {%0,%1,%2,%3};"
                 : "+f"(c[0]), "+f"(c[1]), "+f"(c[2]), "+f"(c[3])
                 : "r"(a[0]), "r"(a[1]), "r"(a[2]), "r"(a[3]), "r"(b[0]), "r"(b[1]));
}
__device__ __forceinline__ void red_add_f32x2(float* addr, float a, float b) {
    asm volatile("red.global.add.v2.f32 [%0], {%1, %2};" :: "l"(addr), "f"(a), "f"(b) : "memory");
}

// ------- prep: counts reset + w1/w2 fp32->fp16 + zero d_out (all DRAM-bound) ---
__global__ void prep_kernel(const float* __restrict__ w1, const float* __restrict__ w2,
                            float* __restrict__ out) {
    if (blockIdx.x == 0 && threadIdx.x < NEXP) g_counts[threadIdx.x] = 0;
    int i = blockIdx.x * 256 + threadIdx.x;
    const int stride = gridDim.x * 256;
#pragma unroll 1
    for (; i < TOT4; i += stride) {
        if (i < 2 * NW4) {
            const bool second = (i >= NW4);
            const int  j      = second ? i - NW4 : i;
            const float4 v = ((const float4*)(second ? w2 : w1))[j];
            __half2* d2 = (__half2*)(second ? g_w2h : g_w1h) + 2 * (size_t)j;
            d2[0] = __floats2half2_rn(v.x, v.y);
            d2[1] = __floats2half2_rn(v.z, v.w);
        } else {
            ((float4*)out)[i - 2 * NW4] = make_float4(0.f, 0.f, 0.f, 0.f);
        }
    }
}

// ---------------- routing (gw staged in smem, float4 x, fused x->fp16) --------
__global__ void __launch_bounds__(256) gate_kernel(const float* __restrict__ x,
                                                   const float* __restrict__ gw) {
    __shared__ float sgw[NEXP][D_MODEL / 4][4];
#pragma unroll
    for (int i = threadIdx.x; i < NEXP * D_MODEL / 4; i += 256) {
        const float4 v = ((const float4*)gw)[i];
        const int e = i >> 8, d4 = i & 255;
        sgw[e][d4][0] = v.x; sgw[e][d4][1] = v.y;
        sgw[e][d4][2] = v.z; sgw[e][d4][3] = v.w;
    }
    __syncthreads();

    const int lane  = threadIdx.x & 31;
    const int token = blockIdx.x * 8 + (threadIdx.x >> 5);

    const float4* xr = (const float4*)(x + (size_t)token * D_MODEL);
    uint2*        xh = (uint2*)(g_xh + (size_t)token * D_MODEL);
    float acc[NEXP];
#pragma unroll
    for (int e = 0; e < NEXP; e++) acc[e] = 0.f;

#pragma unroll
    for (int it = 0; it < D_MODEL / 4 / 32; it++) {       // 8 iters
        const int d4 = lane + it * 32;
        const float4 v = xr[d4];
        __half2 h0 = __floats2half2_rn(v.x, v.y);
        __half2 h1 = __floats2half2_rn(v.z, v.w);
        xh[d4] = make_uint2(*(uint32_t*)&h0, *(uint32_t*)&h1);
#pragma unroll
        for (int e = 0; e < NEXP; e++)
            acc[e] += v.x * sgw[e][d4][0] + v.y * sgw[e][d4][1]
                    + v.z * sgw[e][d4][2] + v.w * sgw[e][d4][3];
    }
#pragma unroll
    for (int e = 0; e < NEXP; e++) {
#pragma unroll
        for (int off = 16; off > 0; off >>= 1)
            acc[e] += __shfl_xor_sync(0xFFFFFFFFu, acc[e], off);
    }
    if (lane == 0) {
        float v0 = -1e30f, v1 = -1e30f;
        int   i0 = 0,      i1 = 0;
#pragma unroll
        for (int e = 0; e < NEXP; e++) {
            const float v = acc[e];
            if (v > v0)      { v1 = v0; i1 = i0; v0 = v; i0 = e; }
            else if (v > v1) { v1 = v;  i1 = e; }
        }
        const float p0 = 1.f / (1.f + __expf(v1 - v0));
        const float p1 = 1.f - p0;
        int s0 = atomicAdd(&g_counts[i0], 1);
        g_tokens[i0 * MAXM + s0] = token;
        g_gatew [i0 * MAXM + s0] = p0;
        int s1 = atomicAdd(&g_counts[i1], 1);
        g_tokens[i1 * MAXM + s1] = token;
        g_gatew [i1 * MAXM + s1] = p1;
    }
}

// ---------------- grouped FFN GEMM (r8 configuration) ----------------
// SECOND=false: H[r,:] = relu(X[tok(r),:] @ W1[e]^T)          K=1024, N=4096
// SECOND=true : out[tok(r),:] += gate(r)*(H[r,:] @ W2[e]^T)   K=4096, N=1024
template <bool SECOND>
__global__ void __launch_bounds__(128, 2) ffn_kernel(float* __restrict__ out) {
    extern __shared__ __align__(128) char sm[];
    __shared__ const __half* srcA[BM];

    const int e   = blockIdx.z;
    const int cnt = g_counts[e];
    const int m0  = blockIdx.x * BM;
    if (m0 >= cnt) return;
    const int n0  = blockIdx.y * BN;
    constexpr int KDIM = SECOND ? F_DIM : D_MODEL;
    constexpr int KT   = KDIM / BK;

    const int tid    = threadIdx.x;
    const int lane   = tid & 31;
    const int wid    = tid >> 5;
    const int warp_m = wid & 1;        // 2 warps in M (64 rows each)
    const int warp_n = (wid >> 1) & 1; // 2 warps in N (64 cols each)

    {
        int r = m0 + tid; if (r >= cnt) r = cnt - 1;
        srcA[tid] = SECOND ? g_H + ((size_t)e * MAXM + r) * F_DIM
                           : g_xh + (size_t)g_tokens[e * MAXM + r] * D_MODEL;
    }
    __syncthreads();

    const __half*  wb  = (SECOND ? g_w2h : g_w1h) + (size_t)e * F_DIM * D_MODEL;
    const uint32_t smb = smem_u32(sm);

    auto load_stage = [&](int st, int kt) {
        const uint32_t aw = smb + st * STG_B;
        const uint32_t bw = aw + A_BYTES;
        const int k0 = kt * BK;
#pragma unroll
        for (int i = 0; i < 8; i++) {                   // A: 1024 16B chunks / 128 thr
            const int idx = tid + i * 128;
            const int row = idx >> 3, c = idx & 7;
            cp_async16(aw + row * 128 + ((c ^ (row & 7)) << 4), srcA[row] + k0 + c * 8);
        }
#pragma unroll
        for (int i = 0; i < 8; i++) {                   // B: 1024 16B chunks
            const int idx = tid + i * 128;
            const int row = idx >> 3, c = idx & 7;
            cp_async16(bw + row * 128 + ((c ^ (row & 7)) << 4),
                       wb + (size_t)(n0 + row) * KDIM + k0 + c * 8);
        }
    };

    auto load_frags = [&](int s, uint32_t (*af)[4], uint32_t (*bf)[2],
                          uint32_t ab, uint32_t bb) {
        const int kk8 = s * 2;
#pragma unroll
        for (int mt = 0; mt < 4; mt++) {
            const int row = warp_m * 64 + mt * 16 + (lane & 15);
            const int k8  = kk8 + (lane >> 4);
            ldm4(af[mt][0], af[mt][1], af[mt][2], af[mt][3],
                 ab + row * 128 + ((k8 ^ (row & 7)) << 4));
        }
#pragma unroll
        for (int i = 0; i < 4; i++) {        // each ldm4 -> two n8k16 B frags
            const int row = warp_n * 64 + i * 16 + ((lane >> 4) << 3) + (lane & 7);
            const int k8  = kk8 + ((lane >> 3) & 1);
            ldm4(bf[2 * i][0], bf[2 * i][1], bf[2 * i + 1][0], bf[2 * i + 1][1],
                 bb + row * 128 + ((k8 ^ (row & 7)) << 4));
        }
    };

    float acc[4][8][4] = {};

    load_stage(0, 0); cp_commit();
    load_stage(1, 1); cp_commit();

#pragma unroll 1
    for (int kt = 0; kt < KT; kt++) {
        cp_wait1();
        __syncthreads();

        const int kn = kt + 2;
        if (kn < KT) load_stage(kn % NST, kn);
        cp_commit();

        const uint32_t ab = smb + (kt % NST) * STG_B;
        const uint32_t bb = ab + A_BYTES;

        uint32_t af[2][4][4], bf[2][8][2];
        load_frags(0, af[0], bf[0], ab, bb);
#pragma unroll
        for (int s = 0; s < 4; s++) {            // 4 k16 steps, double-buffered frags
            if (s < 3) load_frags(s + 1, af[(s + 1) & 1], bf[(s + 1) & 1], ab, bb);
            const int cur = s & 1;
#pragma unroll
            for (int mt = 0; mt < 4; mt++)
#pragma unroll
                for (int nt = 0; nt < 8; nt++)
                    mma_16816(acc[mt][nt], af[cur][mt], bf[cur][nt]);
        }
    }

    // ---- epilogue ----
    const int rbase = m0 + warp_m * 64 + (lane >> 2);
    const int cb    = n0 + warp_n * 64 + (lane & 3) * 2;
    if (!SECOND) {
#pragma unroll
        for (int mt = 0; mt < 4; mt++)
#pragma unroll
            for (int half = 0; half < 2; half++) {
                const int r = rbase + mt * 16 + half * 8;
                if (r < cnt) {
                    __half* hrow = g_H + ((size_t)e * MAXM + r) * F_DIM;
#pragma unroll
                    for (int nt = 0; nt < 8; nt++) {
                        const float v0 = fmaxf(acc[mt][nt][half * 2 + 0], 0.f);
                        const float v1 = fmaxf(acc[mt][nt][half * 2 + 1], 0.f);
                        *(__half2*)&hrow[cb + nt * 8] = __floats2half2_rn(v0, v1);
                    }
                }
            }
    } else {
#pragma unroll
        for (int mt = 0; mt < 4; mt++)
#pragma unroll
            for (int half = 0; half < 2; half++) {
                const int r = rbase + mt * 16 + half * 8;
                if (r < cnt) {
                    const int   tok = g_tokens[e * MAXM + r];
                    const float gwv = g_gatew[e * MAXM + r];
                    float* orow = out + (size_t)tok * D_MODEL;
#pragma unroll
                    for (int nt = 0; nt < 8; nt++)
                        red_add_f32x2(&orow[cb + nt * 8],
                                      acc[mt][nt][half * 2 + 0] * gwv,
                                      acc[mt][nt][half * 2 + 1] * gwv);
                }
            }
    }
}

// ---------------- launch ----------------
extern "C" void kernel_launch(void* const* d_in, const int* in_sizes, int n_in,
                              void* d_out, int out_size) {
    const float* x   = (const float*)d_in[0];
    const float* gw  = (const float*)d_in[1];
    const float* w1  = (const float*)d_in[2];
    const float* w2  = (const float*)d_in[3];
    float*       out = (float*)d_out;

    cudaFuncSetAttribute(ffn_kernel<false>, cudaFuncAttributeMaxDynamicSharedMemorySize, SMEM_REQ);
    cudaFuncSetAttribute(ffn_kernel<true>,  cudaFuncAttributeMaxDynamicSharedMemorySize, SMEM_REQ);

    prep_kernel<<<18432, 256>>>(w1, w2, out);   // counts reset + w1/w2 convert + zero out
    gate_kernel<<<NTOK / 8, 256>>>(x, gw);      // routes + converts x

    ffn_kernel<false><<<dim3(MAXM / BM, F_DIM / BN, NEXP), 128, SMEM_REQ>>>(nullptr);
    ffn_kernel<true ><<<dim3(MAXM / BM, D_MODEL / BN, NEXP), 128, SMEM_REQ>>>(out);
}